// round 16
// baseline (speedup 1.0000x reference)
#include <cuda_runtime.h>
#include <cuda_bf16.h>
#include <cuda_fp16.h>
#include <math.h>
#include <stdint.h>

// Problem constants
#define BSZ 4
#define SEQ 2048
#define DM 1024
#define NH 16
#define HD 64
#define MB 32
#define ROWS_TOTAL (BSZ * SEQ)          // 8192
#define SCALE 0.17677669529663687f      // 1/sqrt(32)
#define LOG2E 1.4426950408889634f

// ---------------------------------------------------------------------------
// Scratch (no allocations allowed -> __device__ globals)
// ---------------------------------------------------------------------------
__device__ __align__(16) __half g_Vf[ROWS_TOTAL * DM];
__device__ __align__(16) __half g_xf[ROWS_TOTAL * DM];
__device__ __align__(16) __half g_AOf[ROWS_TOTAL * DM];
__device__ __align__(16) __half g_QEf[ROWS_TOTAL * NH * MB];
__device__ __align__(16) __half g_KEf[ROWS_TOTAL * NH * MB];
__device__ __align__(16) __half g_Wqf[DM * DM];
__device__ __align__(16) __half g_Wkf[DM * DM];
__device__ __align__(16) __half g_Wvf[DM * DM];
__device__ __align__(16) __half g_Wof[DM * DM];

// ---------------------------------------------------------------------------
// Helpers
// ---------------------------------------------------------------------------
static __device__ __forceinline__ uint32_t smem_u32(const void* p) {
    return (uint32_t)__cvta_generic_to_shared(p);
}

static __device__ __forceinline__ uint32_t pack2h(float a, float b) {
    __half2 t = __floats2half2_rn(a, b);
    return *(uint32_t*)&t;
}

static __device__ __forceinline__ uint32_t h2exp2u(uint32_t x) {
    uint32_t r;
    asm volatile("ex2.approx.f16x2 %0, %1;" : "=r"(r) : "r"(x));
    return r;
}

static __device__ __forceinline__ void ldmx4(uint32_t& r0, uint32_t& r1,
                                             uint32_t& r2, uint32_t& r3,
                                             uint32_t addr) {
    asm volatile("ldmatrix.sync.aligned.m8n8.x4.shared.b16 {%0,%1,%2,%3}, [%4];"
                 : "=r"(r0), "=r"(r1), "=r"(r2), "=r"(r3) : "r"(addr));
}

static __device__ __forceinline__ void ldmx4t(uint32_t& r0, uint32_t& r1,
                                              uint32_t& r2, uint32_t& r3,
                                              uint32_t addr) {
    asm volatile("ldmatrix.sync.aligned.m8n8.x4.trans.shared.b16 {%0,%1,%2,%3}, [%4];"
                 : "=r"(r0), "=r"(r1), "=r"(r2), "=r"(r3) : "r"(addr));
}

static __device__ __forceinline__ void ldmx2t(uint32_t& r0, uint32_t& r1,
                                              uint32_t addr) {
    asm volatile("ldmatrix.sync.aligned.m8n8.x2.trans.shared.b16 {%0,%1}, [%2];"
                 : "=r"(r0), "=r"(r1) : "r"(addr));
}

static __device__ __forceinline__ void mma16816h(float* d, const uint32_t* a,
                                                 const uint32_t* b) {
    asm volatile(
        "mma.sync.aligned.m16n8k16.row.col.f32.f16.f16.f32 "
        "{%0,%1,%2,%3}, {%4,%5,%6,%7}, {%8,%9}, {%0,%1,%2,%3};"
        : "+f"(d[0]), "+f"(d[1]), "+f"(d[2]), "+f"(d[3])
        : "r"(a[0]), "r"(a[1]), "r"(a[2]), "r"(a[3]), "r"(b[0]), "r"(b[1]));
}

static __device__ __forceinline__ void cp16(uint32_t dst, const void* src) {
    asm volatile("cp.async.cg.shared.global [%0], [%1], 16;" :: "r"(dst), "l"(src));
}
static __device__ __forceinline__ void cp_commit() {
    asm volatile("cp.async.commit_group;");
}
template<int N> static __device__ __forceinline__ void cp_wait() {
    asm volatile("cp.async.wait_group %0;" :: "n"(N));
}

// ---------------------------------------------------------------------------
// Fused fp32 -> fp16 conversion: 4 weight matrices + x in ONE launch.
// ---------------------------------------------------------------------------
#define CONV_BLOCKS (4 * 1024 + 8192)    // 12288

__global__ __launch_bounds__(256) void conv_all(
    const float* __restrict__ x,
    const float* __restrict__ w0, const float* __restrict__ w1,
    const float* __restrict__ w2, const float* __restrict__ w3,
    __half* __restrict__ xf,
    __half* __restrict__ d0, __half* __restrict__ d1,
    __half* __restrict__ d2, __half* __restrict__ d3)
{
    int blk = blockIdx.x;
    const float* s; __half* d; int i;
    if (blk < 4096) {
        int w = blk >> 10;
        s = (w == 0) ? w0 : (w == 1) ? w1 : (w == 2) ? w2 : w3;
        d = (w == 0) ? d0 : (w == 1) ? d1 : (w == 2) ? d2 : d3;
        i = (blk & 1023) * 256 + threadIdx.x;
    } else {
        s = x; d = xf;
        i = (blk - 4096) * 256 + threadIdx.x;
    }
    float4 v = ((const float4*)s)[i];
    uint2 o;
    o.x = pack2h(v.x, v.y);
    o.y = pack2h(v.z, v.w);
    ((uint2*)d)[i] = o;
}

// ---------------------------------------------------------------------------
// GEMM geometry: 128 threads / 4 warps, warp tile 32x128, CTA tile 128x128,
// BK=64, 3-stage cp.async ring (wait<1> -> 2 iterations of latency cover),
// one barrier per K-iter.
// ---------------------------------------------------------------------------
#define GKP 72
#define GEMM_SMEM (3 * 2 * 128 * GKP * 2)   // 110592 bytes

// ---------------------------------------------------------------------------
// Fused QKV GEMM + witness encoder.
// grid (24, 64): which = blockIdx.x>>3 selects {Q, K, V}.
// ---------------------------------------------------------------------------
__global__ __launch_bounds__(128, 2) void gemm_qkv_enc(
    const __half* __restrict__ Ax,
    const __half* __restrict__ Bq, const __half* __restrict__ Bk,
    const __half* __restrict__ Bv,
    const float* __restrict__ Wenc,
    __half* __restrict__ QE, __half* __restrict__ KE, __half* __restrict__ Cv)
{
    extern __shared__ __align__(16) char smem[];
    const int tid  = threadIdx.x;
    const int wid  = tid >> 5;
    const int lane = tid & 31;
    const int which = blockIdx.x >> 3;
    const int bcol  = (blockIdx.x & 7) * 128;
    const int brow  = blockIdx.y * 128;
    const int wm   = wid * 32;

    const __half* B = (which == 0) ? Bq : ((which == 1) ? Bk : Bv);

    auto buf = [&](int s, int a) -> __half* {
        return (__half*)smem + (size_t)(s * 2 + a) * 128 * GKP;
    };
    auto stage = [&](int s, int kt) {
#pragma unroll
        for (int i = 0; i < 16; i++) {
            int c = tid + i * 128;          // 0..2047
            int a = c >> 10;                // 0..1
            int cc = c & 1023;
            int row = cc >> 3;
            int part = (cc & 7) << 3;
            const __half* g = (a == 0)
                ? Ax + (size_t)(brow + row) * DM + kt * 64 + part
                : B  + (size_t)(bcol + row) * DM + kt * 64 + part;
            cp16(smem_u32(buf(s, a) + row * GKP + part), g);
        }
    };

    float acc[2][16][4];
#pragma unroll
    for (int mi = 0; mi < 2; mi++)
#pragma unroll
        for (int ni = 0; ni < 16; ni++)
#pragma unroll
            for (int j = 0; j < 4; j++) acc[mi][ni][j] = 0.f;

    const int fr = lane & 15;
    const int fc = (lane >> 4) << 3;

    stage(0, 0); cp_commit();
    stage(1, 1); cp_commit();

    for (int kt = 0; kt < 16; kt++) {
        if (kt < 15) cp_wait<1>(); else cp_wait<0>();
        __syncthreads();
        if (kt < 14) { stage((kt + 2) % 3, kt + 2); cp_commit(); }

        const int cur = kt % 3;
        const __half* pA = buf(cur, 0);
        const __half* pB = buf(cur, 1);

#pragma unroll
        for (int ks = 0; ks < 4; ks++) {
            const int kof = ks * 16 + fc;
            uint32_t a[2][4];
#pragma unroll
            for (int mi = 0; mi < 2; mi++)
                ldmx4(a[mi][0], a[mi][1], a[mi][2], a[mi][3],
                      smem_u32(pA + (wm + mi * 16 + fr) * GKP + kof));
            uint32_t b[16][2];
#pragma unroll
            for (int nq = 0; nq < 8; nq++) {
                uint32_t r0, r1, r2, r3;
                ldmx4(r0, r1, r2, r3, smem_u32(pB + (nq * 16 + fr) * GKP + kof));
                b[nq * 2 + 0][0] = r0; b[nq * 2 + 0][1] = r2;
                b[nq * 2 + 1][0] = r1; b[nq * 2 + 1][1] = r3;
            }
#pragma unroll
            for (int mi = 0; mi < 2; mi++)
#pragma unroll
                for (int ni = 0; ni < 16; ni++)
                    mma16816h(acc[mi][ni], a[mi], b[ni]);
        }
    }

    const int er = lane >> 2;
    const int ec = (lane & 3) * 2;

    if (which == 2) {
        // ---- V epilogue: direct fp16 store ----
#pragma unroll
        for (int mi = 0; mi < 2; mi++) {
#pragma unroll
            for (int ni = 0; ni < 16; ni++) {
                __half* cp0 = Cv + (size_t)(brow + wm + mi * 16 + er) * DM + bcol + ni * 8 + ec;
                *(uint32_t*)cp0 = pack2h(acc[mi][ni][0], acc[mi][ni][1]);
                __half* cp1 = cp0 + 8 * DM;
                *(uint32_t*)cp1 = pack2h(acc[mi][ni][2], acc[mi][ni][3]);
            }
        }
        return;
    }

    // ---- Q/K epilogue: fused encoder, tile = heads hA, hA+1 ----
    __half* E = (which == 0) ? QE : KE;
    const float scale = (which == 0) ? (SCALE * LOG2E) : 1.0f;
    const int hA = bcol >> 6;

    __half* sX = (__half*)smem;                   // 128 x 136 (34816 B)
    __half* sW = (__half*)smem + 128 * 136;       // 2 x 64 x 40 (10240 B)

    __syncthreads();    // stage buffers dead; about to overwrite

    // store acc -> sX (fp16), stride 136 halves (conflict-free)
#pragma unroll
    for (int mi = 0; mi < 2; mi++) {
#pragma unroll
        for (int ni = 0; ni < 16; ni++) {
            int col = ni * 8 + ec;
            *(uint32_t*)&sX[(wm + mi * 16 + er) * 136 + col] =
                pack2h(acc[mi][ni][0], acc[mi][ni][1]);
            *(uint32_t*)&sX[(wm + mi * 16 + er + 8) * 136 + col] =
                pack2h(acc[mi][ni][2], acc[mi][ni][3]);
        }
    }
    // load Wenc for the 2 heads -> sW (fp32 -> fp16)
#pragma unroll
    for (int i = 0; i < 16; i++) {
        int idx = tid + i * 128;        // 0..2047
        int hh = idx >> 10;
        int rem = idx & 1023;
        int d = rem >> 4;
        int m = (rem & 15) * 2;
        float2 w = *(const float2*)&Wenc[(size_t)(hA + hh) * HD * MB + d * MB + m];
        *(uint32_t*)&sW[hh * 2560 + d * 40 + m] = pack2h(w.x, w.y);
    }
    __syncthreads();

#pragma unroll
    for (int hh = 0; hh < 2; hh++) {
        float eacc[2][4][4];
#pragma unroll
        for (int mi = 0; mi < 2; mi++)
#pragma unroll
            for (int nt = 0; nt < 4; nt++)
#pragma unroll
                for (int j = 0; j < 4; j++) eacc[mi][nt][j] = 0.f;

#pragma unroll
        for (int kc = 0; kc < 4; kc++) {
            uint32_t a[2][4];
#pragma unroll
            for (int mi = 0; mi < 2; mi++)
                ldmx4(a[mi][0], a[mi][1], a[mi][2], a[mi][3],
                      smem_u32(&sX[(wm + mi * 16 + fr) * 136 + hh * 64 + kc * 16 + fc]));
#pragma unroll
            for (int nb = 0; nb < 2; nb++) {
                uint32_t r0, r1, r2, r3;
                uint32_t b0[2], b1[2];
                ldmx4t(r0, r1, r2, r3,
                       smem_u32(&sW[hh * 2560 + (kc * 16 + fr) * 40 + nb * 16 + fc]));
                b0[0] = r0; b0[1] = r1; b1[0] = r2; b1[1] = r3;
#pragma unroll
                for (int mi = 0; mi < 2; mi++) {
                    mma16816h(eacc[mi][nb * 2 + 0], a[mi], b0);
                    mma16816h(eacc[mi][nb * 2 + 1], a[mi], b1);
                }
            }
        }

        const int h = hA + hh;
#pragma unroll
        for (int mi = 0; mi < 2; mi++) {
            const size_t r0g = (size_t)(brow + wm + mi * 16 + er);
#pragma unroll
            for (int nt = 0; nt < 4; nt++) {
                int m = nt * 8 + ec;
                *(uint32_t*)&E[(r0g * NH + h) * MB + m] =
                    pack2h(tanhf(eacc[mi][nt][0]) * scale,
                           tanhf(eacc[mi][nt][1]) * scale);
                *(uint32_t*)&E[((r0g + 8) * NH + h) * MB + m] =
                    pack2h(tanhf(eacc[mi][nt][2]) * scale,
                           tanhf(eacc[mi][nt][3]) * scale);
            }
        }
    }
}

// ---------------------------------------------------------------------------
// AO @ Wo^T GEMM, 1-term fp16, fp32 out. 3-stage ring, plain epilogue.
// ---------------------------------------------------------------------------
__global__ __launch_bounds__(128, 2) void gemm_ao(
    const __half* __restrict__ Aa, const __half* __restrict__ B,
    float* __restrict__ Cf)
{
    extern __shared__ __align__(16) char smem[];
    const int tid  = threadIdx.x;
    const int wid  = tid >> 5;
    const int lane = tid & 31;
    const int brow = blockIdx.y * 128;
    const int bcol = blockIdx.x * 128;
    const int wm   = wid * 32;

    auto buf = [&](int s, int a) -> __half* {
        return (__half*)smem + (size_t)(s * 2 + a) * 128 * GKP;
    };
    auto stage = [&](int s, int kt) {
#pragma unroll
        for (int i = 0; i < 16; i++) {
            int c = tid + i * 128;
            int a = c >> 10;
            int cc = c & 1023;
            int row = cc >> 3;
            int part = (cc & 7) << 3;
            const __half* g = (a == 0)
                ? Aa + (size_t)(brow + row) * DM + kt * 64 + part
                : B  + (size_t)(bcol + row) * DM + kt * 64 + part;
            cp16(smem_u32(buf(s, a) + row * GKP + part), g);
        }
    };

    float acc[2][16][4];
#pragma unroll
    for (int mi = 0; mi < 2; mi++)
#pragma unroll
        for (int ni = 0; ni < 16; ni++)
#pragma unroll
            for (int j = 0; j < 4; j++) acc[mi][ni][j] = 0.f;

    const int fr = lane & 15;
    const int fc = (lane >> 4) << 3;

    stage(0, 0); cp_commit();
    stage(1, 1); cp_commit();

    for (int kt = 0; kt < 16; kt++) {
        if (kt < 15) cp_wait<1>(); else cp_wait<0>();
        __syncthreads();
        if (kt < 14) { stage((kt + 2) % 3, kt + 2); cp_commit(); }

        const int cur = kt % 3;
        const __half* pA = buf(cur, 0);
        const __half* pB = buf(cur, 1);

#pragma unroll
        for (int ks = 0; ks < 4; ks++) {
            const int kof = ks * 16 + fc;
            uint32_t a[2][4];
#pragma unroll
            for (int mi = 0; mi < 2; mi++)
                ldmx4(a[mi][0], a[mi][1], a[mi][2], a[mi][3],
                      smem_u32(pA + (wm + mi * 16 + fr) * GKP + kof));
            uint32_t b[16][2];
#pragma unroll
            for (int nq = 0; nq < 8; nq++) {
                uint32_t r0, r1, r2, r3;
                ldmx4(r0, r1, r2, r3, smem_u32(pB + (nq * 16 + fr) * GKP + kof));
                b[nq * 2 + 0][0] = r0; b[nq * 2 + 0][1] = r2;
                b[nq * 2 + 1][0] = r1; b[nq * 2 + 1][1] = r3;
            }
#pragma unroll
            for (int mi = 0; mi < 2; mi++)
#pragma unroll
                for (int ni = 0; ni < 16; ni++)
                    mma16816h(acc[mi][ni], a[mi], b[ni]);
        }
    }

    const int er = lane >> 2;
    const int ec = (lane & 3) * 2;
#pragma unroll
    for (int mi = 0; mi < 2; mi++) {
#pragma unroll
        for (int ni = 0; ni < 16; ni++) {
            float* cp0 = Cf + (size_t)(brow + wm + mi * 16 + er) * DM + bcol + ni * 8 + ec;
            *(float2*)cp0 = make_float2(acc[mi][ni][0], acc[mi][ni][1]);
            float* cp1 = cp0 + 8 * DM;
            *(float2*)cp1 = make_float2(acc[mi][ni][2], acc[mi][ni][3]);
        }
    }
}

// ---------------------------------------------------------------------------
// Tensor-core flash attention, 128 threads / 4 warps x 32 q-rows each.
// scores arrive as s*log2e; p = ex2.approx.f16x2; row-sums via CONSTANT
// ones fragment. 3-stage cp.async ring, one barrier per 128-key tile.
// ---------------------------------------------------------------------------
#define AK 40
#define AV 72
#define ATTN_STAGE ((128 * AK + 128 * AV) * 2)    // 28672 bytes
#define ATTN_SMEM (3 * ATTN_STAGE)                // 86016 bytes

__global__ __launch_bounds__(128, 2) void attn_tc(
    const __half* __restrict__ QEf, const __half* __restrict__ KEf,
    const __half* __restrict__ Vf, __half* __restrict__ AOf)
{
    extern __shared__ __align__(16) char smem[];

    const int tid  = threadIdx.x;
    const int wid  = tid >> 5;
    const int lane = tid & 31;
    const int h = blockIdx.y;
    const int b = blockIdx.z;
    const size_t base = (size_t)b * SEQ;
    const int q0 = blockIdx.x * 128;
    const int wm = wid * 32;
    const int fr = lane & 15;
    const int fc = (lane >> 4) << 3;
    const int gid = lane >> 2;
    const int tig = lane & 3;

    auto bufK = [&](int s) -> __half* {
        return (__half*)(smem + (size_t)s * ATTN_STAGE);
    };
    auto bufV = [&](int s) -> __half* {
        return (__half*)(smem + (size_t)s * ATTN_STAGE) + 128 * AK;
    };
    auto stage = [&](int s, int kt) {
        const int k0 = kt * 128;
        __half* sK = bufK(s);
        __half* sV = bufV(s);
#pragma unroll
        for (int i = 0; i < 4; i++) {
            int c = tid + i * 128;
            int row = c >> 2;
            int part = (c & 3) << 3;
            cp16(smem_u32(sK + row * AK + part),
                 KEf + (base + k0 + row) * (NH * MB) + h * MB + part);
        }
#pragma unroll
        for (int i = 0; i < 8; i++) {
            int c = tid + i * 128;
            int row = c >> 3;
            int part = (c & 7) << 3;
            cp16(smem_u32(sV + row * AV + part),
                 Vf + (base + k0 + row) * DM + h * HD + part);
        }
    };

    // ---- stage Q into buffer 0's K region; plant ones rows 0..15 in V buf 0 ----
    {
        __half* sQ = bufK(0);
#pragma unroll
        for (int i = 0; i < 4; i++) {
            int c = tid + i * 128;
            int row = c >> 2;
            int part = (c & 3) << 3;
            size_t g = (base + q0 + row) * (NH * MB) + h * MB + part;
            *(uint4*)&sQ[row * AK + part] = *(const uint4*)&QEf[g];
        }
        if (tid < 16) {
            uint4 ones = make_uint4(0x00003C00u, 0u, 0u, 0u);
            *(uint4*)&bufV(0)[tid * AV + 64] = ones;
        }
    }
    __syncthreads();
    uint32_t qh[2][2][4];
    uint32_t bo[2];
    {
        __half* sQ = bufK(0);
#pragma unroll
        for (int mi = 0; mi < 2; mi++)
#pragma unroll
            for (int kc = 0; kc < 2; kc++)
                ldmx4(qh[mi][kc][0], qh[mi][kc][1], qh[mi][kc][2], qh[mi][kc][3],
                      smem_u32(&sQ[(wm + mi * 16 + fr) * AK + kc * 16 + fc]));
        ldmx2t(bo[0], bo[1], smem_u32(&bufV(0)[fr * AV + 64]));
    }
    __syncthreads();

    float oacc[2][8][4];
#pragma unroll
    for (int mi = 0; mi < 2; mi++)
#pragma unroll
        for (int nt = 0; nt < 8; nt++)
#pragma unroll
            for (int j = 0; j < 4; j++) oacc[mi][nt][j] = 0.f;
    float lacc[2][4];
#pragma unroll
    for (int mi = 0; mi < 2; mi++)
#pragma unroll
        for (int j = 0; j < 4; j++) lacc[mi][j] = 0.f;

    stage(0, 0); cp_commit();
    stage(1, 1); cp_commit();

    for (int kt = 0; kt < 16; kt++) {
        if (kt < 15) cp_wait<1>(); else cp_wait<0>();
        __syncthreads();
        if (kt < 14) { stage((kt + 2) % 3, kt + 2); cp_commit(); }

        const int cur = kt % 3;
        __half* sK = bufK(cur);
        __half* sV = bufV(cur);

#pragma unroll
        for (int g8 = 0; g8 < 8; g8++) {
            float sa[2][2][4];
#pragma unroll
            for (int mi = 0; mi < 2; mi++)
#pragma unroll
                for (int nt = 0; nt < 2; nt++)
#pragma unroll
                    for (int j = 0; j < 4; j++) sa[mi][nt][j] = 0.f;
#pragma unroll
            for (int kc = 0; kc < 2; kc++) {
                uint32_t r0, r1, r2, r3;
                uint32_t b0[2], b1[2];
                ldmx4(r0, r1, r2, r3,
                      smem_u32(&sK[(g8 * 16 + fr) * AK + kc * 16 + fc]));
                b0[0] = r0; b0[1] = r2; b1[0] = r1; b1[1] = r3;
#pragma unroll
                for (int mi = 0; mi < 2; mi++) {
                    mma16816h(sa[mi][0], qh[mi][kc], b0);
                    mma16816h(sa[mi][1], qh[mi][kc], b1);
                }
            }
            uint32_t ph[2][4];
#pragma unroll
            for (int mi = 0; mi < 2; mi++) {
                ph[mi][0] = h2exp2u(pack2h(sa[mi][0][0], sa[mi][0][1]));
                ph[mi][1] = h2exp2u(pack2h(sa[mi][0][2], sa[mi][0][3]));
                ph[mi][2] = h2exp2u(pack2h(sa[mi][1][0], sa[mi][1][1]));
                ph[mi][3] = h2exp2u(pack2h(sa[mi][1][2], sa[mi][1][3]));
            }
#pragma unroll
            for (int nb = 0; nb < 4; nb++) {
                uint32_t r0, r1, r2, r3;
                uint32_t v0[2], v1[2];
                ldmx4t(r0, r1, r2, r3,
                       smem_u32(&sV[(g8 * 16 + fr) * AV + nb * 16 + fc]));
                v0[0] = r0; v0[1] = r1; v1[0] = r2; v1[1] = r3;
#pragma unroll
                for (int mi = 0; mi < 2; mi++) {
                    mma16816h(oacc[mi][nb * 2 + 0], ph[mi], v0);
                    mma16816h(oacc[mi][nb * 2 + 1], ph[mi], v1);
                }
            }
#pragma unroll
            for (int mi = 0; mi < 2; mi++)
                mma16816h(lacc[mi], ph[mi], bo);
        }
    }

#pragma unroll
    for (int mi = 0; mi < 2; mi++) {
        const float lr  = __shfl_sync(0xffffffffu, lacc[mi][0], gid * 4);
        const float lr8 = __shfl_sync(0xffffffffu, lacc[mi][2], gid * 4);
        const float inv  = 1.f / lr;
        const float inv8 = 1.f / lr8;
        const size_t row0 = base + q0 + wm + mi * 16 + gid;
#pragma unroll
        for (int nt = 0; nt < 8; nt++) {
            int col = h * HD + nt * 8 + tig * 2;
            *(uint32_t*)&AOf[row0 * DM + col] =
                pack2h(oacc[mi][nt][0] * inv, oacc[mi][nt][1] * inv);
            *(uint32_t*)&AOf[(row0 + 8) * DM + col] =
                pack2h(oacc[mi][nt][2] * inv8, oacc[mi][nt][3] * inv8);
        }
    }
}

// ---------------------------------------------------------------------------
// Launch
// ---------------------------------------------------------------------------
extern "C" void kernel_launch(void* const* d_in, const int* in_sizes, int n_in,
                              void* d_out, int out_size)
{
    const float* x    = (const float*)d_in[0];
    const float* Wq   = (const float*)d_in[1];
    const float* Wk   = (const float*)d_in[2];
    const float* Wv   = (const float*)d_in[3];
    const float* Wenc = (const float*)d_in[4];
    const float* Wo   = (const float*)d_in[5];
    float* out = (float*)d_out;

    __half *Vf, *xf, *AOf, *QEf, *KEf;
    __half *Wqf, *Wkf, *Wvf, *Wof;
    cudaGetSymbolAddress((void**)&Vf,  g_Vf);
    cudaGetSymbolAddress((void**)&xf,  g_xf);
    cudaGetSymbolAddress((void**)&AOf, g_AOf);
    cudaGetSymbolAddress((void**)&QEf, g_QEf);
    cudaGetSymbolAddress((void**)&KEf, g_KEf);
    cudaGetSymbolAddress((void**)&Wqf, g_Wqf);
    cudaGetSymbolAddress((void**)&Wkf, g_Wkf);
    cudaGetSymbolAddress((void**)&Wvf, g_Wvf);
    cudaGetSymbolAddress((void**)&Wof, g_Wof);

    static bool init = false;
    if (!init) {
        cudaFuncSetAttribute(gemm_qkv_enc, cudaFuncAttributeMaxDynamicSharedMemorySize,
                             GEMM_SMEM);
        cudaFuncSetAttribute(gemm_ao, cudaFuncAttributeMaxDynamicSharedMemorySize,
                             GEMM_SMEM);
        cudaFuncSetAttribute(attn_tc, cudaFuncAttributeMaxDynamicSharedMemorySize,
                             ATTN_SMEM);
        init = true;
    }

    conv_all<<<CONV_BLOCKS, 256>>>(x, Wq, Wk, Wv, Wo,
                                   xf, Wqf, Wkf, Wvf, Wof);

    dim3 gQKV(3 * DM / 128, ROWS_TOTAL / 128);   // (24, 64)
    gemm_qkv_enc<<<gQKV, 128, GEMM_SMEM>>>(xf, Wqf, Wkf, Wvf, Wenc,
                                           QEf, KEf, Vf);

    dim3 gAttn(SEQ / 128, NH, BSZ);              // (16, 16, 4)
    attn_tc<<<gAttn, 128, ATTN_SMEM>>>(QEf, KEf, Vf, AOf);

    dim3 gWo(DM / 128, ROWS_TOTAL / 128);        // (8, 64)
    gemm_ao<<<gWo, 128, GEMM_SMEM>>>(AOf, Wof, out);
}

// round 17
// speedup vs baseline: 1.0788x; 1.0788x over previous
#include <cuda_runtime.h>
#include <cuda_bf16.h>
#include <cuda_fp16.h>
#include <math.h>
#include <stdint.h>

// Problem constants
#define BSZ 4
#define SEQ 2048
#define DM 1024
#define NH 16
#define HD 64
#define MB 32
#define ROWS_TOTAL (BSZ * SEQ)          // 8192
#define SCALE 0.17677669529663687f      // 1/sqrt(32)
#define LOG2E 1.4426950408889634f

// ---------------------------------------------------------------------------
// Scratch (no allocations allowed -> __device__ globals)
// ---------------------------------------------------------------------------
__device__ __align__(16) __half g_Vf[ROWS_TOTAL * DM];
__device__ __align__(16) __half g_xf[ROWS_TOTAL * DM];
__device__ __align__(16) __half g_AOf[ROWS_TOTAL * DM];
__device__ __align__(16) __half g_QEf[ROWS_TOTAL * NH * MB];
__device__ __align__(16) __half g_KEf[ROWS_TOTAL * NH * MB];
__device__ __align__(16) __half g_Wqf[DM * DM];
__device__ __align__(16) __half g_Wkf[DM * DM];
__device__ __align__(16) __half g_Wvf[DM * DM];
__device__ __align__(16) __half g_Wof[DM * DM];

// ---------------------------------------------------------------------------
// Helpers
// ---------------------------------------------------------------------------
static __device__ __forceinline__ uint32_t smem_u32(const void* p) {
    return (uint32_t)__cvta_generic_to_shared(p);
}

static __device__ __forceinline__ uint32_t pack2h(float a, float b) {
    __half2 t = __floats2half2_rn(a, b);
    return *(uint32_t*)&t;
}

static __device__ __forceinline__ uint32_t h2exp2u(uint32_t x) {
    uint32_t r;
    asm volatile("ex2.approx.f16x2 %0, %1;" : "=r"(r) : "r"(x));
    return r;
}

static __device__ __forceinline__ void ldmx4(uint32_t& r0, uint32_t& r1,
                                             uint32_t& r2, uint32_t& r3,
                                             uint32_t addr) {
    asm volatile("ldmatrix.sync.aligned.m8n8.x4.shared.b16 {%0,%1,%2,%3}, [%4];"
                 : "=r"(r0), "=r"(r1), "=r"(r2), "=r"(r3) : "r"(addr));
}

static __device__ __forceinline__ void ldmx4t(uint32_t& r0, uint32_t& r1,
                                              uint32_t& r2, uint32_t& r3,
                                              uint32_t addr) {
    asm volatile("ldmatrix.sync.aligned.m8n8.x4.trans.shared.b16 {%0,%1,%2,%3}, [%4];"
                 : "=r"(r0), "=r"(r1), "=r"(r2), "=r"(r3) : "r"(addr));
}

static __device__ __forceinline__ void ldmx2t(uint32_t& r0, uint32_t& r1,
                                              uint32_t addr) {
    asm volatile("ldmatrix.sync.aligned.m8n8.x2.trans.shared.b16 {%0,%1}, [%2];"
                 : "=r"(r0), "=r"(r1) : "r"(addr));
}

static __device__ __forceinline__ void mma16816h(float* d, const uint32_t* a,
                                                 const uint32_t* b) {
    asm volatile(
        "mma.sync.aligned.m16n8k16.row.col.f32.f16.f16.f32 "
        "{%0,%1,%2,%3}, {%4,%5,%6,%7}, {%8,%9}, {%0,%1,%2,%3};"
        : "+f"(d[0]), "+f"(d[1]), "+f"(d[2]), "+f"(d[3])
        : "r"(a[0]), "r"(a[1]), "r"(a[2]), "r"(a[3]), "r"(b[0]), "r"(b[1]));
}

static __device__ __forceinline__ void cp16(uint32_t dst, const void* src) {
    asm volatile("cp.async.cg.shared.global [%0], [%1], 16;" :: "r"(dst), "l"(src));
}
static __device__ __forceinline__ void cp_commit() {
    asm volatile("cp.async.commit_group;");
}
template<int N> static __device__ __forceinline__ void cp_wait() {
    asm volatile("cp.async.wait_group %0;" :: "n"(N));
}

// ---------------------------------------------------------------------------
// Fused fp32 -> fp16 conversion: 4 weight matrices + x in ONE launch.
// ---------------------------------------------------------------------------
#define CONV_BLOCKS (4 * 1024 + 8192)    // 12288

__global__ __launch_bounds__(256) void conv_all(
    const float* __restrict__ x,
    const float* __restrict__ w0, const float* __restrict__ w1,
    const float* __restrict__ w2, const float* __restrict__ w3,
    __half* __restrict__ xf,
    __half* __restrict__ d0, __half* __restrict__ d1,
    __half* __restrict__ d2, __half* __restrict__ d3)
{
    int blk = blockIdx.x;
    const float* s; __half* d; int i;
    if (blk < 4096) {
        int w = blk >> 10;
        s = (w == 0) ? w0 : (w == 1) ? w1 : (w == 2) ? w2 : w3;
        d = (w == 0) ? d0 : (w == 1) ? d1 : (w == 2) ? d2 : d3;
        i = (blk & 1023) * 256 + threadIdx.x;
    } else {
        s = x; d = xf;
        i = (blk - 4096) * 256 + threadIdx.x;
    }
    float4 v = ((const float4*)s)[i];
    uint2 o;
    o.x = pack2h(v.x, v.y);
    o.y = pack2h(v.z, v.w);
    ((uint2*)d)[i] = o;
}

// ---------------------------------------------------------------------------
// GEMM geometry: 128 threads / 4 warps, warp tile 32x64, CTA tile 128x64,
// BK=64, 2-stage cp.async ring, regs capped at 128 -> 4 CTAs/SM
// (4 warps/SMSP for latency hiding; that is the limiter per round-16 data).
// ---------------------------------------------------------------------------
#define GKP 72
#define GSTAGE (192 * GKP)                 // halves per stage (128 A + 64 B rows)
#define GEMM_SMEM (2 * GSTAGE * 2)         // 55296 bytes

// ---------------------------------------------------------------------------
// Fused QKV GEMM + witness encoder.
// grid (48, 64): which = blockIdx.x>>4 selects {Q, K, V}; bcol = 64-col block
// (= exactly one head for Q/K).
// ---------------------------------------------------------------------------
__global__ __launch_bounds__(128, 4) void gemm_qkv_enc(
    const __half* __restrict__ Ax,
    const __half* __restrict__ Bq, const __half* __restrict__ Bk,
    const __half* __restrict__ Bv,
    const float* __restrict__ Wenc,
    __half* __restrict__ QE, __half* __restrict__ KE, __half* __restrict__ Cv)
{
    extern __shared__ __align__(16) char smem[];
    const int tid  = threadIdx.x;
    const int wid  = tid >> 5;
    const int lane = tid & 31;
    const int which = blockIdx.x >> 4;
    const int bcol  = (blockIdx.x & 15) * 64;
    const int brow  = blockIdx.y * 128;
    const int wm   = wid * 32;

    const __half* B = (which == 0) ? Bq : ((which == 1) ? Bk : Bv);

    auto bufA = [&](int s) -> __half* {
        return (__half*)smem + (size_t)s * GSTAGE;
    };
    auto bufB = [&](int s) -> __half* {
        return bufA(s) + 128 * GKP;
    };
    auto stage = [&](int s, int kt) {
#pragma unroll
        for (int i = 0; i < 12; i++) {
            int c = tid + i * 128;          // 0..1535
            if (i < 8) {                    // A: c < 1024
                int row = c >> 3;
                int part = (c & 7) << 3;
                cp16(smem_u32(bufA(s) + row * GKP + part),
                     Ax + (size_t)(brow + row) * DM + kt * 64 + part);
            } else {                        // B: 64 rows
                int cc = c - 1024;
                int row = cc >> 3;
                int part = (cc & 7) << 3;
                cp16(smem_u32(bufB(s) + row * GKP + part),
                     B + (size_t)(bcol + row) * DM + kt * 64 + part);
            }
        }
    };

    float acc[2][8][4];
#pragma unroll
    for (int mi = 0; mi < 2; mi++)
#pragma unroll
        for (int ni = 0; ni < 8; ni++)
#pragma unroll
            for (int j = 0; j < 4; j++) acc[mi][ni][j] = 0.f;

    const int fr = lane & 15;
    const int fc = (lane >> 4) << 3;

    stage(0, 0); cp_commit();

    for (int kt = 0; kt < 16; kt++) {
        cp_wait<0>();
        __syncthreads();
        if (kt < 15) { stage((kt + 1) & 1, kt + 1); cp_commit(); }

        const int cur = kt & 1;
        const __half* pA = bufA(cur);
        const __half* pB = bufB(cur);

#pragma unroll
        for (int ks = 0; ks < 4; ks++) {
            const int kof = ks * 16 + fc;
            uint32_t a[2][4];
#pragma unroll
            for (int mi = 0; mi < 2; mi++)
                ldmx4(a[mi][0], a[mi][1], a[mi][2], a[mi][3],
                      smem_u32(pA + (wm + mi * 16 + fr) * GKP + kof));
            uint32_t b[8][2];
#pragma unroll
            for (int nq = 0; nq < 4; nq++) {
                uint32_t r0, r1, r2, r3;
                ldmx4(r0, r1, r2, r3, smem_u32(pB + (nq * 16 + fr) * GKP + kof));
                b[nq * 2 + 0][0] = r0; b[nq * 2 + 0][1] = r2;
                b[nq * 2 + 1][0] = r1; b[nq * 2 + 1][1] = r3;
            }
#pragma unroll
            for (int mi = 0; mi < 2; mi++)
#pragma unroll
                for (int ni = 0; ni < 8; ni++)
                    mma16816h(acc[mi][ni], a[mi], b[ni]);
        }
    }

    const int er = lane >> 2;
    const int ec = (lane & 3) * 2;

    if (which == 2) {
        // ---- V epilogue: direct fp16 store ----
#pragma unroll
        for (int mi = 0; mi < 2; mi++) {
#pragma unroll
            for (int ni = 0; ni < 8; ni++) {
                __half* cp0 = Cv + (size_t)(brow + wm + mi * 16 + er) * DM + bcol + ni * 8 + ec;
                *(uint32_t*)cp0 = pack2h(acc[mi][ni][0], acc[mi][ni][1]);
                __half* cp1 = cp0 + 8 * DM;
                *(uint32_t*)cp1 = pack2h(acc[mi][ni][2], acc[mi][ni][3]);
            }
        }
        return;
    }

    // ---- Q/K epilogue: fused encoder, tile = single head h ----
    __half* E = (which == 0) ? QE : KE;
    const float scale = (which == 0) ? (SCALE * LOG2E) : 1.0f;
    const int h = bcol >> 6;

    __half* sX = (__half*)smem;                   // 128 x 72 (18432 B)
    __half* sW = (__half*)smem + 128 * 72;        // 64 x 40  (5120 B)

    __syncthreads();    // stage buffers dead; about to overwrite

    // store acc -> sX (fp16), stride 72 halves
#pragma unroll
    for (int mi = 0; mi < 2; mi++) {
#pragma unroll
        for (int ni = 0; ni < 8; ni++) {
            int col = ni * 8 + ec;
            *(uint32_t*)&sX[(wm + mi * 16 + er) * 72 + col] =
                pack2h(acc[mi][ni][0], acc[mi][ni][1]);
            *(uint32_t*)&sX[(wm + mi * 16 + er + 8) * 72 + col] =
                pack2h(acc[mi][ni][2], acc[mi][ni][3]);
        }
    }
    // load Wenc for head h -> sW (fp32 -> fp16): 64x32 = 1024 float2
#pragma unroll
    for (int i = 0; i < 8; i++) {
        int idx = tid + i * 128;        // 0..1023
        int d = idx >> 4;
        int m = (idx & 15) * 2;
        float2 w = *(const float2*)&Wenc[(size_t)h * HD * MB + d * MB + m];
        *(uint32_t*)&sW[d * 40 + m] = pack2h(w.x, w.y);
    }
    __syncthreads();

    float eacc[2][4][4];
#pragma unroll
    for (int mi = 0; mi < 2; mi++)
#pragma unroll
        for (int nt = 0; nt < 4; nt++)
#pragma unroll
            for (int j = 0; j < 4; j++) eacc[mi][nt][j] = 0.f;

#pragma unroll
    for (int kc = 0; kc < 4; kc++) {
        uint32_t a[2][4];
#pragma unroll
        for (int mi = 0; mi < 2; mi++)
            ldmx4(a[mi][0], a[mi][1], a[mi][2], a[mi][3],
                  smem_u32(&sX[(wm + mi * 16 + fr) * 72 + kc * 16 + fc]));
#pragma unroll
        for (int nb = 0; nb < 2; nb++) {
            uint32_t r0, r1, r2, r3;
            uint32_t b0[2], b1[2];
            ldmx4t(r0, r1, r2, r3,
                   smem_u32(&sW[(kc * 16 + fr) * 40 + nb * 16 + fc]));
            b0[0] = r0; b0[1] = r1; b1[0] = r2; b1[1] = r3;
#pragma unroll
            for (int mi = 0; mi < 2; mi++) {
                mma16816h(eacc[mi][nb * 2 + 0], a[mi], b0);
                mma16816h(eacc[mi][nb * 2 + 1], a[mi], b1);
            }
        }
    }

#pragma unroll
    for (int mi = 0; mi < 2; mi++) {
        const size_t r0g = (size_t)(brow + wm + mi * 16 + er);
#pragma unroll
        for (int nt = 0; nt < 4; nt++) {
            int m = nt * 8 + ec;
            *(uint32_t*)&E[(r0g * NH + h) * MB + m] =
                pack2h(tanhf(eacc[mi][nt][0]) * scale,
                       tanhf(eacc[mi][nt][1]) * scale);
            *(uint32_t*)&E[((r0g + 8) * NH + h) * MB + m] =
                pack2h(tanhf(eacc[mi][nt][2]) * scale,
                       tanhf(eacc[mi][nt][3]) * scale);
        }
    }
}

// ---------------------------------------------------------------------------
// AO @ Wo^T GEMM, 1-term fp16, fp32 out. Same 128x64 tile, 4 CTAs/SM.
// ---------------------------------------------------------------------------
__global__ __launch_bounds__(128, 4) void gemm_ao(
    const __half* __restrict__ Aa, const __half* __restrict__ B,
    float* __restrict__ Cf)
{
    extern __shared__ __align__(16) char smem[];
    const int tid  = threadIdx.x;
    const int wid  = tid >> 5;
    const int lane = tid & 31;
    const int brow = blockIdx.y * 128;
    const int bcol = blockIdx.x * 64;
    const int wm   = wid * 32;

    auto bufA = [&](int s) -> __half* {
        return (__half*)smem + (size_t)s * GSTAGE;
    };
    auto bufB = [&](int s) -> __half* {
        return bufA(s) + 128 * GKP;
    };
    auto stage = [&](int s, int kt) {
#pragma unroll
        for (int i = 0; i < 12; i++) {
            int c = tid + i * 128;
            if (i < 8) {
                int row = c >> 3;
                int part = (c & 7) << 3;
                cp16(smem_u32(bufA(s) + row * GKP + part),
                     Aa + (size_t)(brow + row) * DM + kt * 64 + part);
            } else {
                int cc = c - 1024;
                int row = cc >> 3;
                int part = (cc & 7) << 3;
                cp16(smem_u32(bufB(s) + row * GKP + part),
                     B + (size_t)(bcol + row) * DM + kt * 64 + part);
            }
        }
    };

    float acc[2][8][4];
#pragma unroll
    for (int mi = 0; mi < 2; mi++)
#pragma unroll
        for (int ni = 0; ni < 8; ni++)
#pragma unroll
            for (int j = 0; j < 4; j++) acc[mi][ni][j] = 0.f;

    const int fr = lane & 15;
    const int fc = (lane >> 4) << 3;

    stage(0, 0); cp_commit();

    for (int kt = 0; kt < 16; kt++) {
        cp_wait<0>();
        __syncthreads();
        if (kt < 15) { stage((kt + 1) & 1, kt + 1); cp_commit(); }

        const int cur = kt & 1;
        const __half* pA = bufA(cur);
        const __half* pB = bufB(cur);

#pragma unroll
        for (int ks = 0; ks < 4; ks++) {
            const int kof = ks * 16 + fc;
            uint32_t a[2][4];
#pragma unroll
            for (int mi = 0; mi < 2; mi++)
                ldmx4(a[mi][0], a[mi][1], a[mi][2], a[mi][3],
                      smem_u32(pA + (wm + mi * 16 + fr) * GKP + kof));
            uint32_t b[8][2];
#pragma unroll
            for (int nq = 0; nq < 4; nq++) {
                uint32_t r0, r1, r2, r3;
                ldmx4(r0, r1, r2, r3, smem_u32(pB + (nq * 16 + fr) * GKP + kof));
                b[nq * 2 + 0][0] = r0; b[nq * 2 + 0][1] = r2;
                b[nq * 2 + 1][0] = r1; b[nq * 2 + 1][1] = r3;
            }
#pragma unroll
            for (int mi = 0; mi < 2; mi++)
#pragma unroll
                for (int ni = 0; ni < 8; ni++)
                    mma16816h(acc[mi][ni], a[mi], b[ni]);
        }
    }

    const int er = lane >> 2;
    const int ec = (lane & 3) * 2;
#pragma unroll
    for (int mi = 0; mi < 2; mi++) {
#pragma unroll
        for (int ni = 0; ni < 8; ni++) {
            float* cp0 = Cf + (size_t)(brow + wm + mi * 16 + er) * DM + bcol + ni * 8 + ec;
            *(float2*)cp0 = make_float2(acc[mi][ni][0], acc[mi][ni][1]);
            float* cp1 = cp0 + 8 * DM;
            *(float2*)cp1 = make_float2(acc[mi][ni][2], acc[mi][ni][3]);
        }
    }
}

// ---------------------------------------------------------------------------
// Tensor-core flash attention, 128 threads / 4 warps x 32 q-rows each.
// scores arrive as s*log2e; p = ex2.approx.f16x2; row-sums via CONSTANT
// ones fragment. 3-stage cp.async ring, one barrier per 128-key tile.
// ---------------------------------------------------------------------------
#define AK 40
#define AV 72
#define ATTN_STAGE ((128 * AK + 128 * AV) * 2)    // 28672 bytes
#define ATTN_SMEM (3 * ATTN_STAGE)                // 86016 bytes

__global__ __launch_bounds__(128, 2) void attn_tc(
    const __half* __restrict__ QEf, const __half* __restrict__ KEf,
    const __half* __restrict__ Vf, __half* __restrict__ AOf)
{
    extern __shared__ __align__(16) char smem[];

    const int tid  = threadIdx.x;
    const int wid  = tid >> 5;
    const int lane = tid & 31;
    const int h = blockIdx.y;
    const int b = blockIdx.z;
    const size_t base = (size_t)b * SEQ;
    const int q0 = blockIdx.x * 128;
    const int wm = wid * 32;
    const int fr = lane & 15;
    const int fc = (lane >> 4) << 3;
    const int gid = lane >> 2;
    const int tig = lane & 3;

    auto bufK = [&](int s) -> __half* {
        return (__half*)(smem + (size_t)s * ATTN_STAGE);
    };
    auto bufV = [&](int s) -> __half* {
        return (__half*)(smem + (size_t)s * ATTN_STAGE) + 128 * AK;
    };
    auto stage = [&](int s, int kt) {
        const int k0 = kt * 128;
        __half* sK = bufK(s);
        __half* sV = bufV(s);
#pragma unroll
        for (int i = 0; i < 4; i++) {
            int c = tid + i * 128;
            int row = c >> 2;
            int part = (c & 3) << 3;
            cp16(smem_u32(sK + row * AK + part),
                 KEf + (base + k0 + row) * (NH * MB) + h * MB + part);
        }
#pragma unroll
        for (int i = 0; i < 8; i++) {
            int c = tid + i * 128;
            int row = c >> 3;
            int part = (c & 7) << 3;
            cp16(smem_u32(sV + row * AV + part),
                 Vf + (base + k0 + row) * DM + h * HD + part);
        }
    };

    // ---- stage Q into buffer 0's K region; plant ones rows 0..15 in V buf 0 ----
    {
        __half* sQ = bufK(0);
#pragma unroll
        for (int i = 0; i < 4; i++) {
            int c = tid + i * 128;
            int row = c >> 2;
            int part = (c & 3) << 3;
            size_t g = (base + q0 + row) * (NH * MB) + h * MB + part;
            *(uint4*)&sQ[row * AK + part] = *(const uint4*)&QEf[g];
        }
        if (tid < 16) {
            uint4 ones = make_uint4(0x00003C00u, 0u, 0u, 0u);
            *(uint4*)&bufV(0)[tid * AV + 64] = ones;
        }
    }
    __syncthreads();
    uint32_t qh[2][2][4];
    uint32_t bo[2];
    {
        __half* sQ = bufK(0);
#pragma unroll
        for (int mi = 0; mi < 2; mi++)
#pragma unroll
            for (int kc = 0; kc < 2; kc++)
                ldmx4(qh[mi][kc][0], qh[mi][kc][1], qh[mi][kc][2], qh[mi][kc][3],
                      smem_u32(&sQ[(wm + mi * 16 + fr) * AK + kc * 16 + fc]));
        ldmx2t(bo[0], bo[1], smem_u32(&bufV(0)[fr * AV + 64]));
    }
    __syncthreads();

    float oacc[2][8][4];
#pragma unroll
    for (int mi = 0; mi < 2; mi++)
#pragma unroll
        for (int nt = 0; nt < 8; nt++)
#pragma unroll
            for (int j = 0; j < 4; j++) oacc[mi][nt][j] = 0.f;
    float lacc[2][4];
#pragma unroll
    for (int mi = 0; mi < 2; mi++)
#pragma unroll
        for (int j = 0; j < 4; j++) lacc[mi][j] = 0.f;

    stage(0, 0); cp_commit();
    stage(1, 1); cp_commit();

    for (int kt = 0; kt < 16; kt++) {
        if (kt < 15) cp_wait<1>(); else cp_wait<0>();
        __syncthreads();
        if (kt < 14) { stage((kt + 2) % 3, kt + 2); cp_commit(); }

        const int cur = kt % 3;
        __half* sK = bufK(cur);
        __half* sV = bufV(cur);

#pragma unroll
        for (int g8 = 0; g8 < 8; g8++) {
            float sa[2][2][4];
#pragma unroll
            for (int mi = 0; mi < 2; mi++)
#pragma unroll
                for (int nt = 0; nt < 2; nt++)
#pragma unroll
                    for (int j = 0; j < 4; j++) sa[mi][nt][j] = 0.f;
#pragma unroll
            for (int kc = 0; kc < 2; kc++) {
                uint32_t r0, r1, r2, r3;
                uint32_t b0[2], b1[2];
                ldmx4(r0, r1, r2, r3,
                      smem_u32(&sK[(g8 * 16 + fr) * AK + kc * 16 + fc]));
                b0[0] = r0; b0[1] = r2; b1[0] = r1; b1[1] = r3;
#pragma unroll
                for (int mi = 0; mi < 2; mi++) {
                    mma16816h(sa[mi][0], qh[mi][kc], b0);
                    mma16816h(sa[mi][1], qh[mi][kc], b1);
                }
            }
            uint32_t ph[2][4];
#pragma unroll
            for (int mi = 0; mi < 2; mi++) {
                ph[mi][0] = h2exp2u(pack2h(sa[mi][0][0], sa[mi][0][1]));
                ph[mi][1] = h2exp2u(pack2h(sa[mi][0][2], sa[mi][0][3]));
                ph[mi][2] = h2exp2u(pack2h(sa[mi][1][0], sa[mi][1][1]));
                ph[mi][3] = h2exp2u(pack2h(sa[mi][1][2], sa[mi][1][3]));
            }
#pragma unroll
            for (int nb = 0; nb < 4; nb++) {
                uint32_t r0, r1, r2, r3;
                uint32_t v0[2], v1[2];
                ldmx4t(r0, r1, r2, r3,
                       smem_u32(&sV[(g8 * 16 + fr) * AV + nb * 16 + fc]));
                v0[0] = r0; v0[1] = r1; v1[0] = r2; v1[1] = r3;
#pragma unroll
                for (int mi = 0; mi < 2; mi++) {
                    mma16816h(oacc[mi][nb * 2 + 0], ph[mi], v0);
                    mma16816h(oacc[mi][nb * 2 + 1], ph[mi], v1);
                }
            }
#pragma unroll
            for (int mi = 0; mi < 2; mi++)
                mma16816h(lacc[mi], ph[mi], bo);
        }
    }

#pragma unroll
    for (int mi = 0; mi < 2; mi++) {
        const float lr  = __shfl_sync(0xffffffffu, lacc[mi][0], gid * 4);
        const float lr8 = __shfl_sync(0xffffffffu, lacc[mi][2], gid * 4);
        const float inv  = 1.f / lr;
        const float inv8 = 1.f / lr8;
        const size_t row0 = base + q0 + wm + mi * 16 + gid;
#pragma unroll
        for (int nt = 0; nt < 8; nt++) {
            int col = h * HD + nt * 8 + tig * 2;
            *(uint32_t*)&AOf[row0 * DM + col] =
                pack2h(oacc[mi][nt][0] * inv, oacc[mi][nt][1] * inv);
            *(uint32_t*)&AOf[(row0 + 8) * DM + col] =
                pack2h(oacc[mi][nt][2] * inv8, oacc[mi][nt][3] * inv8);
        }
    }
}

// ---------------------------------------------------------------------------
// Launch
// ---------------------------------------------------------------------------
extern "C" void kernel_launch(void* const* d_in, const int* in_sizes, int n_in,
                              void* d_out, int out_size)
{
    const float* x    = (const float*)d_in[0];
    const float* Wq   = (const float*)d_in[1];
    const float* Wk   = (const float*)d_in[2];
    const float* Wv   = (const float*)d_in[3];
    const float* Wenc = (const float*)d_in[4];
    const float* Wo   = (const float*)d_in[5];
    float* out = (float*)d_out;

    __half *Vf, *xf, *AOf, *QEf, *KEf;
    __half *Wqf, *Wkf, *Wvf, *Wof;
    cudaGetSymbolAddress((void**)&Vf,  g_Vf);
    cudaGetSymbolAddress((void**)&xf,  g_xf);
    cudaGetSymbolAddress((void**)&AOf, g_AOf);
    cudaGetSymbolAddress((void**)&QEf, g_QEf);
    cudaGetSymbolAddress((void**)&KEf, g_KEf);
    cudaGetSymbolAddress((void**)&Wqf, g_Wqf);
    cudaGetSymbolAddress((void**)&Wkf, g_Wkf);
    cudaGetSymbolAddress((void**)&Wvf, g_Wvf);
    cudaGetSymbolAddress((void**)&Wof, g_Wof);

    static bool init = false;
    if (!init) {
        cudaFuncSetAttribute(gemm_qkv_enc, cudaFuncAttributeMaxDynamicSharedMemorySize,
                             GEMM_SMEM);
        cudaFuncSetAttribute(gemm_ao, cudaFuncAttributeMaxDynamicSharedMemorySize,
                             GEMM_SMEM);
        cudaFuncSetAttribute(attn_tc, cudaFuncAttributeMaxDynamicSharedMemorySize,
                             ATTN_SMEM);
        init = true;
    }

    conv_all<<<CONV_BLOCKS, 256>>>(x, Wq, Wk, Wv, Wo,
                                   xf, Wqf, Wkf, Wvf, Wof);

    dim3 gQKV(3 * DM / 64, ROWS_TOTAL / 128);    // (48, 64)
    gemm_qkv_enc<<<gQKV, 128, GEMM_SMEM>>>(xf, Wqf, Wkf, Wvf, Wenc,
                                           QEf, KEf, Vf);

    dim3 gAttn(SEQ / 128, NH, BSZ);              // (16, 16, 4)
    attn_tc<<<gAttn, 128, ATTN_SMEM>>>(QEf, KEf, Vf, AOf);

    dim3 gWo(DM / 64, ROWS_TOTAL / 128);         // (16, 64)
    gemm_ao<<<gWo, 128, GEMM_SMEM>>>(AOf, Wof, out);
}